// round 8
// baseline (speedup 1.0000x reference)
#include <cuda_runtime.h>
#include <cuda_bf16.h>

// SE block: B=32, H=W=56 (HW=3136), C=256, R=16
#define HW     3136
#define CCH    256
#define NB     32
#define NS     49              // hw chunks per batch
#define CHUNK  64              // hw rows per unit
#define NUNIT  (NB * NS)       // 1568 units, u = b*49 + s
#define NBLK   784             // = NUNIT/2: exactly 2 pool + 2 scale units per block

// Scratch (__device__ globals per allocation-free rule)
__device__ float g_partial[NUNIT * CCH];   // [u][c]
__device__ float g_gate[NB * CCH];
__device__ unsigned int g_count = 0;       // barrier arrivals (self-resetting)
__device__ unsigned int g_gen   = 0;       // barrier generation (monotonic)

__device__ __forceinline__ void grid_barrier() {
    __syncthreads();
    if (threadIdx.x == 0) {
        unsigned gen = *((volatile unsigned*)&g_gen);
        __threadfence();
        if (atomicAdd(&g_count, 1u) == NBLK - 1) {
            g_count = 0;
            __threadfence();
            atomicAdd(&g_gen, 1u);
        } else {
            while (*((volatile unsigned*)&g_gen) == gen) { }
        }
        __threadfence();
    }
    __syncthreads();
}

struct SM {
    float4 red[256];        // pool reduction / MLP partials (4 KB)
    float  s_s[CCH];
    float  s_h[16];
    float  s_w1[CCH * 16];  // 16 KB
};

__device__ __forceinline__ void do_pool(int u, int t, int c4, int ho,
                                        const float4* __restrict__ x4, SM* sm) {
    const int b = u / NS, s = u - b * NS;
    const size_t base = ((size_t)b * HW + (size_t)s * CHUNK + ho) * (CCH / 4) + c4;

    float4 acc = make_float4(0.f, 0.f, 0.f, 0.f);
#pragma unroll
    for (int k = 0; k < CHUNK; k += 4) {
        float4 v = x4[base + (size_t)k * (CCH / 4)];
        acc.x += v.x; acc.y += v.y; acc.z += v.z; acc.w += v.w;
    }
    sm->red[t] = acc;
    __syncthreads();
    if (t < 64) {
        float4 a = sm->red[t], e = sm->red[t + 64], f = sm->red[t + 128], h = sm->red[t + 192];
        float4 r = make_float4(a.x + e.x + f.x + h.x,
                               a.y + e.y + f.y + h.y,
                               a.z + e.z + f.z + h.z,
                               a.w + e.w + f.w + h.w);
        reinterpret_cast<float4*>(g_partial)[(size_t)u * (CCH / 4) + t] = r;
    }
    __syncthreads();
}

__device__ __forceinline__ void do_scale(int u, int t, int c4, int ho,
                                         const float4* __restrict__ x4,
                                         float4* __restrict__ o4) {
    const int b = u / NS, s = u - b * NS;

    const float* gp = g_gate + b * CCH + 4 * c4;
    float4 g;
    g.x = __ldcg(gp + 0); g.y = __ldcg(gp + 1);
    g.z = __ldcg(gp + 2); g.w = __ldcg(gp + 3);

    const size_t base = ((size_t)b * HW + (size_t)s * CHUNK + ho) * (CCH / 4) + c4;
#pragma unroll
    for (int k = 0; k < CHUNK; k += 4) {
        const size_t idx = base + (size_t)k * (CCH / 4);
        float4 v = __ldcs(&x4[idx]);   // last use of x: evict-first
        v.x *= g.x; v.y *= g.y; v.z *= g.z; v.w *= g.w;
        __stcs(&o4[idx], v);           // streaming store: don't pollute L2
    }
}

__global__ void __launch_bounds__(256, 6)
k_se(const float* __restrict__ x,
     const float* __restrict__ w1,
     const float* __restrict__ b1,
     const float* __restrict__ w2,
     const float* __restrict__ b2,
     float* __restrict__ out) {
    const int bid = blockIdx.x;
    const int t   = threadIdx.x;
    const int c4  = t & 63;
    const int ho  = t >> 6;

    const float4* x4 = reinterpret_cast<const float4*>(x);
    float4*       o4 = reinterpret_cast<float4*>(out);

    __shared__ SM sm;

    // ---------------- Phase 1: pooling, exactly 2 units per block ----------------
    do_pool(bid,        t, c4, ho, x4, &sm);
    do_pool(bid + NBLK, t, c4, ho, x4, &sm);

    grid_barrier();

    // ---------------- MLP: blocks 0..31, one per batch ----------------
    if (bid < NB) {
        const int b = bid;
#pragma unroll
        for (int i = t; i < CCH * 16; i += 256) sm.s_w1[i] = w1[i];

        float accm = 0.f;
#pragma unroll
        for (int ss = 0; ss < NS; ss++)
            accm += __ldcg(&g_partial[((size_t)b * NS + ss) * CCH + t]);
        sm.s_s[t] = accm * (1.0f / (float)HW);
        __syncthreads();

        // dense1 parallelized: t = grp*16 + cout; 16 groups of 16 k each
        {
            const int cout = t & 15;
            const int grp  = t >> 4;
            float p = 0.f;
#pragma unroll
            for (int k = grp * 16; k < grp * 16 + 16; k++)
                p = fmaf(sm.s_s[k], sm.s_w1[k * 16 + cout], p);
            reinterpret_cast<float*>(sm.red)[t] = p;
        }
        __syncthreads();
        if (t < 16) {
            float h = b1[t];
#pragma unroll
            for (int j = 0; j < 16; j++)
                h += reinterpret_cast<float*>(sm.red)[j * 16 + t];
            sm.s_h[t] = fmaxf(h, 0.f);
        }
        __syncthreads();

        float g = b2[t];
#pragma unroll
        for (int j = 0; j < 16; j++)
            g = fmaf(sm.s_h[j], w2[j * CCH + t], g);
        g_gate[b * CCH + t] = 1.f / (1.f + __expf(-g));
        __threadfence();
    }

    grid_barrier();

    // ---------------- Phase 2: broadcast multiply, same 2 units reversed ----------------
    do_scale(bid + NBLK, t, c4, ho, x4, o4);
    do_scale(bid,        t, c4, ho, x4, o4);
}

extern "C" void kernel_launch(void* const* d_in, const int* in_sizes, int n_in,
                              void* d_out, int out_size) {
    const float* x  = (const float*)d_in[0];
    const float* w1 = (const float*)d_in[1];
    const float* b1 = (const float*)d_in[2];
    const float* w2 = (const float*)d_in[3];
    const float* b2 = (const float*)d_in[4];
    float* out = (float*)d_out;

    k_se<<<NBLK, 256>>>(x, w1, b1, w2, b2, out);
}